// round 16
// baseline (speedup 1.0000x reference)
#include <cuda_runtime.h>
#include <cuda_fp16.h>
#include <math.h>
#include <float.h>
#include <stdint.h>

#define BB 2
#define LL 4096
#define DD 768
#define HH 12
#define DH 64
#define QKV_N (3*DD)
#define MM (BB*LL)

// Scratch (no cudaMalloc allowed)
__device__ __half g_xh[(size_t)MM * DD];
__device__ __half g_wqkvt[(size_t)QKV_N * DD];  // Wqkv^T, [N][K]
__device__ __half g_wot[(size_t)DD * DD];       // Wo^T
__device__ __half g_qkvh[(size_t)MM * QKV_N];   // q pre-scaled by 0.125*log2(e)
__device__ __half g_yh[(size_t)MM * DD];
__device__ int    g_wcnt;                       // Wqkv^T blocks done (of NTRQ)
__device__ int    g_pcnt[64];                   // x-cvt per m-block (of 96)
__device__ int    g_cnt[64];                    // flash (b,qt) completion (of 12)

// ---------------------------------------------------------------------------
// helpers
// ---------------------------------------------------------------------------
__device__ __forceinline__ uint32_t smem_u32(const void* p) {
    uint32_t a;
    asm("{ .reg .u64 t; cvta.to.shared.u64 t, %1; cvt.u32.u64 %0, t; }"
        : "=r"(a) : "l"(p));
    return a;
}
__device__ __forceinline__ void cp16(uint32_t dst, const void* src) {
    asm volatile("cp.async.cg.shared.global [%0], [%1], 16;"
                 :: "r"(dst), "l"(src));
}
#define CP_COMMIT asm volatile("cp.async.commit_group;" ::: "memory")
#define CP_WAIT0  asm volatile("cp.async.wait_group 0;" ::: "memory")

__device__ __forceinline__ void ldsm4(uint32_t* r, uint32_t a) {
    asm volatile("ldmatrix.sync.aligned.m8n8.x4.shared.b16 {%0,%1,%2,%3}, [%4];"
        : "=r"(r[0]), "=r"(r[1]), "=r"(r[2]), "=r"(r[3]) : "r"(a));
}
__device__ __forceinline__ void ldsm4t(uint32_t* r, uint32_t a) {
    asm volatile("ldmatrix.sync.aligned.m8n8.x4.trans.shared.b16 {%0,%1,%2,%3}, [%4];"
        : "=r"(r[0]), "=r"(r[1]), "=r"(r[2]), "=r"(r[3]) : "r"(a));
}
__device__ __forceinline__ void mma16(float* d, const uint32_t* a,
                                      uint32_t b0, uint32_t b1) {
    asm volatile(
        "mma.sync.aligned.m16n8k16.row.col.f32.f16.f16.f32 "
        "{%0,%1,%2,%3}, {%4,%5,%6,%7}, {%8,%9}, {%0,%1,%2,%3};"
        : "+f"(d[0]), "+f"(d[1]), "+f"(d[2]), "+f"(d[3])
        : "r"(a[0]), "r"(a[1]), "r"(a[2]), "r"(a[3]), "r"(b0), "r"(b1));
}
__device__ __forceinline__ uint32_t pack2(float a, float b) {
    __half2 h = __floats2half2_rn(a, b);
    return *reinterpret_cast<uint32_t*>(&h);
}

// ---------------------------------------------------------------------------
// block counts
// ---------------------------------------------------------------------------
#define NTRQ ((QKV_N / 32) * (DD / 32))   // 1728 Wqkv^T blocks
#define NCVT (MM * DD / 4 / 256)          // 6144 x-cvt blocks (96 per m-block)
#define NTRW ((DD / 32) * (DD / 32))      // 576  Wo^T blocks
#define NPREP (NTRQ + NCVT + NTRW)

#define GROW 144
#define GST  36864
#define GDSM (2*GST)
#define QSCALE 0.1803368801111204f   // 0.125 * log2(e)

__device__ __forceinline__ void tr_body(
    const float* __restrict__ in, __half* __restrict__ out,
    int R, int C, int bx, int by, float* tile)
{
    const int tx = threadIdx.x & 31, ty = threadIdx.x >> 5;
    const int c0 = bx * 32, r0 = by * 32;
    for (int j = ty; j < 32; j += 8)
        tile[j * 33 + tx] = in[(size_t)(r0 + j) * C + c0 + tx];
    __syncthreads();
    for (int j = ty; j < 32; j += 8)
        out[(size_t)(c0 + j) * R + r0 + tx] = __float2half_rn(tile[tx * 33 + j]);
}

__device__ __forceinline__ void g_stage(
    const __half* __restrict__ A, const __half* __restrict__ Bt,
    uint32_t as, uint32_t bs, int m0, int n0, int k0, int K, int tid)
{
    const int r = tid >> 3, c = tid & 7;
    const __half* Ap = A + (size_t)(m0 + r) * K + k0 + c * 8;
    const __half* Bp = Bt + (size_t)(n0 + r) * K + k0 + c * 8;
    #pragma unroll
    for (int p = 0; p < 4; p++) {
        cp16(as + (r + p * 32) * GROW + c * 16, Ap + (size_t)(p * 32) * K);
        cp16(bs + (r + p * 32) * GROW + c * 16, Bp + (size_t)(p * 32) * K);
    }
}

__device__ __forceinline__ void gemm_core(
    const __half* __restrict__ A, const __half* __restrict__ Bt,
    uint32_t sbase, int m0, int n0, int K,
    int tid, int warp, int lane, float acc[4][4][4])
{
    const int wm = (warp >> 2) * 64, wn = (warp & 3) * 32;

    g_stage(A, Bt, sbase, sbase + 18432, m0, n0, 0, K, tid);
    CP_COMMIT;

    const int NCH = K / 64;
    for (int ch = 0; ch < NCH; ch++) {
        CP_WAIT0;
        __syncthreads();
        if (ch + 1 < NCH) {
            const uint32_t s = sbase + ((ch + 1) & 1) * GST;
            g_stage(A, Bt, s, s + 18432, m0, n0, (ch + 1) * 64, K, tid);
            CP_COMMIT;
        }
        const uint32_t as = sbase + (ch & 1) * GST;
        const uint32_t bs = as + 18432;
        #pragma unroll
        for (int j = 0; j < 4; j++) {
            const int kk = j * 16;
            uint32_t af[4][4];
            #pragma unroll
            for (int mi = 0; mi < 4; mi++)
                ldsm4(af[mi], as + (wm + mi * 16 + (lane & 15)) * GROW
                              + (kk + ((lane >> 4) << 3)) * 2);
            #pragma unroll
            for (int np = 0; np < 2; np++) {
                uint32_t bf[4];
                ldsm4(bf, bs + (wn + np * 16 + (lane & 7) + ((lane >> 4) << 3)) * GROW
                          + (kk + (((lane >> 3) & 1) << 3)) * 2);
                #pragma unroll
                for (int mi = 0; mi < 4; mi++) {
                    mma16(acc[mi][np * 2],     af[mi], bf[0], bf[1]);
                    mma16(acc[mi][np * 2 + 1], af[mi], bf[2], bf[3]);
                }
            }
        }
        __syncthreads();
    }
}

// ---------------------------------------------------------------------------
// Kernel A: prep (Wqkv^T first, x-cvt by m-block, Wo^T) + qkv gemm (waits on
// counters). Bid order guarantees producers dispatch before consumers.
// Resets g_cnt (used by kernel B). Kernel B resets g_wcnt/g_pcnt for the
// next call.
// ---------------------------------------------------------------------------
#define PG_GRID (NPREP + 1152)

__global__ __launch_bounds__(256) void prep_gemm(
    const float* __restrict__ x, __half* __restrict__ xh,
    const float* __restrict__ Wqkv, __half* __restrict__ wqkvt,
    const float* __restrict__ Wo, __half* __restrict__ wot,
    const float* __restrict__ bqkv, __half* __restrict__ qkv)
{
    extern __shared__ char sm[];
    __shared__ float tile[32 * 33];
    const int tid = threadIdx.x;
    const int bid = blockIdx.x;

    if (bid == 0 && tid < 64) g_cnt[tid] = 0;   // for kernel B (no writer here)

    if (bid < NTRQ) {
        // Wqkv^T block
        tr_body(Wqkv, wqkvt, DD, QKV_N, bid % (QKV_N / 32), bid / (QKV_N / 32), tile);
        __threadfence();
        __syncthreads();
        if (tid == 0) atomicAdd(&g_wcnt, 1);
    } else if (bid < NTRQ + NCVT) {
        // x -> fp16, grouped by 128-row m-block (96 blocks per mb)
        const int cb = bid - NTRQ;
        const int mb = cb / 96, j = cb % 96;
        const int i = mb * 24576 + j * 256 + tid;   // float4 index
        float4 v = ((const float4*)x)[i];
        uint2 u;
        u.x = pack2(v.x, v.y);
        u.y = pack2(v.z, v.w);
        ((uint2*)xh)[i] = u;
        __threadfence();
        __syncthreads();
        if (tid == 0) atomicAdd(&g_pcnt[mb], 1);
    } else if (bid < NPREP) {
        // Wo^T block (consumed only by kernel B -> kernel boundary protects)
        const int tb = bid - NTRQ - NCVT;
        tr_body(Wo, wot, DD, DD, tb % (DD / 32), tb / (DD / 32), tile);
    } else {
        // ---------------- qkv gemm path ----------------
        const int gid = bid - NPREP;
        const int mb = gid / 18, nb = gid % 18;
        const int m0 = mb * 128, n0 = nb * 128;
        const int warp = tid >> 5, lane = tid & 31;
        const int g = lane >> 2, t = lane & 3;
        const int wm = (warp >> 2) * 64, wn = (warp & 3) * 32;

        if (tid == 0) {
            while (atomicAdd(&g_wcnt, 0) < NTRQ) __nanosleep(100);
            while (atomicAdd(&g_pcnt[mb], 0) < 96) __nanosleep(100);
        }
        __syncthreads();
        __threadfence();

        const uint32_t sbase = smem_u32(sm);
        float acc[4][4][4] = {};
        gemm_core(xh, wqkvt, sbase, m0, n0, DD, tid, warp, lane, acc);

        #pragma unroll
        for (int mi = 0; mi < 4; mi++) {
            const int row = m0 + wm + mi * 16 + g;
            #pragma unroll
            for (int nbk = 0; nbk < 4; nbk++) {
                const int col = n0 + wn + nbk * 8 + 2 * t;
                const float b0 = bqkv[col], b1 = bqkv[col + 1];
                const float sc = (col < DD) ? QSCALE : 1.0f;
                *(uint32_t*)(qkv + (size_t)row * QKV_N + col) =
                    pack2((acc[mi][nbk][0] + b0) * sc, (acc[mi][nbk][1] + b1) * sc);
                *(uint32_t*)(qkv + (size_t)(row + 8) * QKV_N + col) =
                    pack2((acc[mi][nbk][2] + b0) * sc, (acc[mi][nbk][3] + b1) * sc);
            }
        }
    }
}

// ---------------------------------------------------------------------------
// Kernel B: fused flash + out-proj (R14 body), plus prep-counter reset for
// the next call.
// ---------------------------------------------------------------------------
#define FROW 144
#define FST  18432
#define FUSED_GRID 1152
#define FUSED_DSM GDSM

__global__ __launch_bounds__(256, 2) void fused(
    const __half* __restrict__ qkv, __half* __restrict__ y,
    const __half* __restrict__ wot, const float* __restrict__ bo,
    float* __restrict__ out)
{
    extern __shared__ char sm[];
    const uint32_t sbase = smem_u32(sm);
    const int tid = threadIdx.x, warp = tid >> 5, lane = tid & 31;
    const int g = lane >> 2, t = lane & 3;
    const int bid = blockIdx.x;

    if (bid == 0 && tid < 64) {         // reset prep counters for next call
        g_pcnt[tid] = 0;
        if (tid == 0) g_wcnt = 0;
    }

    if (bid < 768) {
        // ---------------- flash path ----------------
        const int qt = 31 - (bid / 24);
        const int r24 = bid % 24;
        const int h = r24 % HH, b = r24 / HH;
        const int qbase = qt * 128, wrow = warp * 16;

        const __half* __restrict__ Qg = qkv + (size_t)b * LL * QKV_N + h * DH;
        const __half* __restrict__ Kg = qkv + (size_t)b * LL * QKV_N + DD + h * DH;
        const __half* __restrict__ Vg = qkv + (size_t)b * LL * QKV_N + 2 * DD + h * DH;

        #pragma unroll
        for (int p = 0; p < 4; p++) {
            const int id = p * 256 + tid;
            const int rr = id >> 3, c = id & 7;
            cp16(sbase + rr * FROW + c * 16, Qg + (size_t)(qbase + rr) * QKV_N + c * 8);
        }
        CP_COMMIT; CP_WAIT0;
        __syncthreads();
        uint32_t qf[4][4];
        #pragma unroll
        for (int j = 0; j < 4; j++)
            ldsm4(qf[j], sbase + (wrow + (lane & 15)) * FROW
                         + (j * 16 + ((lane >> 4) << 3)) * 2);
        __syncthreads();

        float o[8][4] = {};
        float l_lo = 0.f, l_hi = 0.f;
        const int ktmax = 2 * (qt + 1);

        #pragma unroll
        for (int p = 0; p < 2; p++) {
            const int id = p * 256 + tid;
            const int rr = id >> 3, c = id & 7;
            cp16(sbase + rr * FROW + c * 16, Kg + (size_t)rr * QKV_N + c * 8);
            cp16(sbase + 9216 + rr * FROW + c * 16, Vg + (size_t)rr * QKV_N + c * 8);
        }
        CP_COMMIT;

        for (int kt = 0; kt < ktmax; kt++) {
            CP_WAIT0;
            __syncthreads();
            if (kt + 1 < ktmax) {
                const uint32_t s = sbase + ((kt + 1) & 1) * FST;
                const int nb2 = (kt + 1) * 64;
                #pragma unroll
                for (int p = 0; p < 2; p++) {
                    const int id = p * 256 + tid;
                    const int rr = id >> 3, c = id & 7;
                    cp16(s + rr * FROW + c * 16, Kg + (size_t)(nb2 + rr) * QKV_N + c * 8);
                    cp16(s + 9216 + rr * FROW + c * 16, Vg + (size_t)(nb2 + rr) * QKV_N + c * 8);
                }
                CP_COMMIT;
            }
            const int kbase = kt * 64;
            if (kbase <= qbase + wrow + 15) {
                const uint32_t ks = sbase + (kt & 1) * FST;
                const uint32_t vs = ks + 9216;

                float s[8][4] = {};
                #pragma unroll
                for (int j = 0; j < 4; j++) {
                    const int kk = j * 16;
                    #pragma unroll
                    for (int np = 0; np < 4; np++) {
                        uint32_t bf[4];
                        ldsm4(bf, ks + (np * 16 + (lane & 7) + ((lane >> 4) << 3)) * FROW
                                  + (kk + (((lane >> 3) & 1) << 3)) * 2);
                        mma16(s[np * 2],     qf[j], bf[0], bf[1]);
                        mma16(s[np * 2 + 1], qf[j], bf[2], bf[3]);
                    }
                }

                if (kbase + 63 > qbase + wrow) {
                    const int row_lo = qbase + wrow + g, row_hi = row_lo + 8;
                    #pragma unroll
                    for (int n = 0; n < 8; n++) {
                        const int c0 = kbase + n * 8 + 2 * t;
                        if (c0 > row_lo)     s[n][0] = -FLT_MAX;
                        if (c0 + 1 > row_lo) s[n][1] = -FLT_MAX;
                        if (c0 > row_hi)     s[n][2] = -FLT_MAX;
                        if (c0 + 1 > row_hi) s[n][3] = -FLT_MAX;
                    }
                }

                #pragma unroll
                for (int n = 0; n < 8; n++) {
                    s[n][0] = exp2f(s[n][0]);
                    s[n][1] = exp2f(s[n][1]);
                    s[n][2] = exp2f(s[n][2]);
                    s[n][3] = exp2f(s[n][3]);
                    l_lo += s[n][0] + s[n][1];
                    l_hi += s[n][2] + s[n][3];
                }

                #pragma unroll
                for (int j = 0; j < 4; j++) {
                    uint32_t pa[4];
                    pa[0] = pack2(s[2 * j][0],     s[2 * j][1]);
                    pa[1] = pack2(s[2 * j][2],     s[2 * j][3]);
                    pa[2] = pack2(s[2 * j + 1][0], s[2 * j + 1][1]);
                    pa[3] = pack2(s[2 * j + 1][2], s[2 * j + 1][3]);
                    const int kk = j * 16;
                    #pragma unroll
                    for (int np = 0; np < 4; np++) {
                        uint32_t bf[4];
                        ldsm4t(bf, vs + (kk + (lane & 7) + (((lane >> 3) & 1) << 3)) * FROW
                                   + (np * 16 + ((lane >> 4) << 3)) * 2);
                        mma16(o[np * 2],     pa, bf[0], bf[1]);
                        mma16(o[np * 2 + 1], pa, bf[2], bf[3]);
                    }
                }
            }
        }

        l_lo += __shfl_xor_sync(0xffffffffu, l_lo, 1);
        l_lo += __shfl_xor_sync(0xffffffffu, l_lo, 2);
        l_hi += __shfl_xor_sync(0xffffffffu, l_hi, 1);
        l_hi += __shfl_xor_sync(0xffffffffu, l_hi, 2);

        const float il_lo = 1.0f / l_lo;
        const float il_hi = 1.0f / l_hi;
        const int row = qbase + wrow + g;
        #pragma unroll
        for (int n = 0; n < 8; n++) {
            const int col = h * DH + n * 8 + 2 * t;
            *(uint32_t*)(y + ((size_t)b * LL + row) * DD + col) =
                pack2(o[n][0] * il_lo, o[n][1] * il_lo);
            *(uint32_t*)(y + ((size_t)b * LL + row + 8) * DD + col) =
                pack2(o[n][2] * il_hi, o[n][3] * il_hi);
        }

        __threadfence();
        __syncthreads();
        if (tid == 0) atomicAdd(&g_cnt[b * 32 + qt], 1);

    } else {
        // ---------------- out-proj path ----------------
        const int pid = bid - 768;
        const int qtp = 31 - (pid / 12);
        const int r12 = pid % 12;
        const int n0 = (r12 % 6) * 128;
        const int pb = r12 / 6;
        const int yy = pb * 32 + qtp;
        const int m0 = yy * 128;

        if (tid == 0) {
            while (atomicAdd(&g_cnt[yy], 0) < HH) __nanosleep(200);
        }
        __syncthreads();
        __threadfence();

        const int wm = (warp >> 2) * 64, wn = (warp & 3) * 32;
        float acc[4][4][4] = {};
        gemm_core(y, wot, sbase, m0, n0, DD, tid, warp, lane, acc);

        #pragma unroll
        for (int mi = 0; mi < 4; mi++) {
            const int row = m0 + wm + mi * 16 + g;
            #pragma unroll
            for (int nbk = 0; nbk < 4; nbk++) {
                const int col = n0 + wn + nbk * 8 + 2 * t;
                const float b0 = bo[col], b1 = bo[col + 1];
                *(float2*)(out + (size_t)row * DD + col) =
                    make_float2(acc[mi][nbk][0] + b0, acc[mi][nbk][1] + b1);
                *(float2*)(out + (size_t)(row + 8) * DD + col) =
                    make_float2(acc[mi][nbk][2] + b0, acc[mi][nbk][3] + b1);
            }
        }
    }
}

// ---------------------------------------------------------------------------
extern "C" void kernel_launch(void* const* d_in, const int* in_sizes, int n_in,
                              void* d_out, int out_size)
{
    (void)in_sizes; (void)n_in; (void)out_size;
    const float* x    = (const float*)d_in[0];
    const float* Wqkv = (const float*)d_in[1];
    const float* bqkv = (const float*)d_in[2];
    const float* Wo   = (const float*)d_in[3];
    const float* bo   = (const float*)d_in[4];
    float* out = (float*)d_out;

    __half *xh, *wqkvt, *wot, *qkvh, *yh;
    cudaGetSymbolAddress((void**)&xh, g_xh);
    cudaGetSymbolAddress((void**)&wqkvt, g_wqkvt);
    cudaGetSymbolAddress((void**)&wot, g_wot);
    cudaGetSymbolAddress((void**)&qkvh, g_qkvh);
    cudaGetSymbolAddress((void**)&yh, g_yh);

    static bool attr_done = false;
    if (!attr_done) {
        cudaFuncSetAttribute(prep_gemm, cudaFuncAttributeMaxDynamicSharedMemorySize, GDSM);
        cudaFuncSetAttribute(fused, cudaFuncAttributeMaxDynamicSharedMemorySize, FUSED_DSM);
        attr_done = true;
    }

    prep_gemm<<<PG_GRID, 256, GDSM>>>(x, xh, Wqkv, wqkvt, Wo, wot, bqkv, qkvh);

    fused<<<FUSED_GRID, 256, FUSED_DSM>>>(qkvh, yh, wot, bo, out);
}

// round 17
// speedup vs baseline: 1.1776x; 1.1776x over previous
#include <cuda_runtime.h>
#include <cuda_fp16.h>
#include <math.h>
#include <float.h>
#include <stdint.h>

#define BB 2
#define LL 4096
#define DD 768
#define HH 12
#define DH 64
#define QKV_N (3*DD)
#define MM (BB*LL)

// Scratch (no cudaMalloc allowed)
__device__ __half g_xh[(size_t)MM * DD];
__device__ __half g_wqkvt[(size_t)QKV_N * DD];  // Wqkv^T, [N][K]
__device__ __half g_wot[(size_t)DD * DD];       // Wo^T
__device__ __half g_qkvh[(size_t)MM * QKV_N];   // q pre-scaled by 0.125*log2(e)
__device__ __half g_yh[(size_t)MM * DD];
__device__ int    g_cnt[64];                    // per (b,qt) head-completion count

// ---------------------------------------------------------------------------
// helpers
// ---------------------------------------------------------------------------
__device__ __forceinline__ uint32_t smem_u32(const void* p) {
    uint32_t a;
    asm("{ .reg .u64 t; cvta.to.shared.u64 t, %1; cvt.u32.u64 %0, t; }"
        : "=r"(a) : "l"(p));
    return a;
}
__device__ __forceinline__ void cp16(uint32_t dst, const void* src) {
    asm volatile("cp.async.cg.shared.global [%0], [%1], 16;"
                 :: "r"(dst), "l"(src));
}
#define CP_COMMIT asm volatile("cp.async.commit_group;" ::: "memory")
#define CP_WAIT(N) asm volatile("cp.async.wait_group %0;" :: "n"(N) : "memory")

__device__ __forceinline__ void ldsm4(uint32_t* r, uint32_t a) {
    asm volatile("ldmatrix.sync.aligned.m8n8.x4.shared.b16 {%0,%1,%2,%3}, [%4];"
        : "=r"(r[0]), "=r"(r[1]), "=r"(r[2]), "=r"(r[3]) : "r"(a));
}
__device__ __forceinline__ void ldsm4t(uint32_t* r, uint32_t a) {
    asm volatile("ldmatrix.sync.aligned.m8n8.x4.trans.shared.b16 {%0,%1,%2,%3}, [%4];"
        : "=r"(r[0]), "=r"(r[1]), "=r"(r[2]), "=r"(r[3]) : "r"(a));
}
__device__ __forceinline__ void mma16(float* d, const uint32_t* a,
                                      uint32_t b0, uint32_t b1) {
    asm volatile(
        "mma.sync.aligned.m16n8k16.row.col.f32.f16.f16.f32 "
        "{%0,%1,%2,%3}, {%4,%5,%6,%7}, {%8,%9}, {%0,%1,%2,%3};"
        : "+f"(d[0]), "+f"(d[1]), "+f"(d[2]), "+f"(d[3])
        : "r"(a[0]), "r"(a[1]), "r"(a[2]), "r"(a[3]), "r"(b0), "r"(b1));
}
__device__ __forceinline__ uint32_t pack2(float a, float b) {
    __half2 h = __floats2half2_rn(a, b);
    return *reinterpret_cast<uint32_t*>(&h);
}

// ---------------------------------------------------------------------------
// merged prep kernel (R11/R14) + counter reset
// ---------------------------------------------------------------------------
#define NCVT (MM * DD / 4 / 256)
#define NTRQ ((QKV_N / 32) * (DD / 32))
#define NTRW ((DD / 32) * (DD / 32))
#define NPREP (NCVT + NTRQ + NTRW)

__device__ __forceinline__ void tr_body(
    const float* __restrict__ in, __half* __restrict__ out,
    int R, int C, int bx, int by, float* tile)
{
    const int tx = threadIdx.x & 31, ty = threadIdx.x >> 5;
    const int c0 = bx * 32, r0 = by * 32;
    for (int j = ty; j < 32; j += 8)
        tile[j * 33 + tx] = in[(size_t)(r0 + j) * C + c0 + tx];
    __syncthreads();
    for (int j = ty; j < 32; j += 8)
        out[(size_t)(c0 + j) * R + r0 + tx] = __float2half_rn(tile[tx * 33 + j]);
}

__global__ __launch_bounds__(256) void prep(
    const float* __restrict__ x, __half* __restrict__ xh,
    const float* __restrict__ Wqkv, __half* __restrict__ wqkvt,
    const float* __restrict__ Wo, __half* __restrict__ wot)
{
    __shared__ float tile[32 * 33];
    const int bid = blockIdx.x;
    if (bid == 0 && threadIdx.x < 64) g_cnt[threadIdx.x] = 0;
    if (bid < NCVT) {
        const int i = bid * 256 + threadIdx.x;
        float4 v = ((const float4*)x)[i];
        uint2 u;
        u.x = pack2(v.x, v.y);
        u.y = pack2(v.z, v.w);
        ((uint2*)xh)[i] = u;
    } else if (bid < NCVT + NTRQ) {
        const int tb = bid - NCVT;
        tr_body(Wqkv, wqkvt, DD, QKV_N, tb % (QKV_N / 32), tb / (QKV_N / 32), tile);
    } else {
        const int tb = bid - NCVT - NTRQ;
        tr_body(Wo, wot, DD, DD, tb % (DD / 32), tb / (DD / 32), tile);
    }
}

// ---------------------------------------------------------------------------
// GEMM staging (shared)
// ---------------------------------------------------------------------------
#define GROW 144
#define GST  36864
#define GDSM2 (2*GST)
#define GDSM3 (3*GST)
#define QSCALE 0.1803368801111204f   // 0.125 * log2(e)

__device__ __forceinline__ void g_stage(
    const __half* __restrict__ A, const __half* __restrict__ Bt,
    uint32_t as, uint32_t bs, int m0, int n0, int k0, int K, int tid)
{
    const int r = tid >> 3, c = tid & 7;
    const __half* Ap = A + (size_t)(m0 + r) * K + k0 + c * 8;
    const __half* Bp = Bt + (size_t)(n0 + r) * K + k0 + c * 8;
    #pragma unroll
    for (int p = 0; p < 4; p++) {
        cp16(as + (r + p * 32) * GROW + c * 16, Ap + (size_t)(p * 32) * K);
        cp16(bs + (r + p * 32) * GROW + c * 16, Bp + (size_t)(p * 32) * K);
    }
}

__device__ __forceinline__ void g_compute_chunk(
    uint32_t as, uint32_t bs, int wm, int wn, int lane, float acc[4][4][4])
{
    #pragma unroll
    for (int j = 0; j < 4; j++) {
        const int kk = j * 16;
        uint32_t af[4][4];
        #pragma unroll
        for (int mi = 0; mi < 4; mi++)
            ldsm4(af[mi], as + (wm + mi * 16 + (lane & 15)) * GROW
                          + (kk + ((lane >> 4) << 3)) * 2);
        #pragma unroll
        for (int np = 0; np < 2; np++) {
            uint32_t bf[4];
            ldsm4(bf, bs + (wn + np * 16 + (lane & 7) + ((lane >> 4) << 3)) * GROW
                      + (kk + (((lane >> 3) & 1) << 3)) * 2);
            #pragma unroll
            for (int mi = 0; mi < 4; mi++) {
                mma16(acc[mi][np * 2],     af[mi], bf[0], bf[1]);
                mma16(acc[mi][np * 2 + 1], af[mi], bf[2], bf[3]);
            }
        }
    }
}

// ---------------------------------------------------------------------------
// QKV gemm: 3-stage cp.async ring (prefetch depth 2, wait_group 1).
// ---------------------------------------------------------------------------
__global__ __launch_bounds__(256) void gemm_qkv(
    const __half* __restrict__ A, const __half* __restrict__ Bt,
    const float* __restrict__ bias, __half* __restrict__ C,
    int M, int N, int K)
{
    extern __shared__ char sm[];
    const uint32_t sbase = smem_u32(sm);
    const int tid = threadIdx.x, warp = tid >> 5, lane = tid & 31;
    const int g = lane >> 2, t = lane & 3;
    const int wm = (warp >> 2) * 64, wn = (warp & 3) * 32;
    const int m0 = blockIdx.y * 128, n0 = blockIdx.x * 128;

    float acc[4][4][4] = {};

    const int NCH = K / 64;   // 12
    // prestage chunks 0 and 1
    g_stage(A, Bt, sbase, sbase + 18432, m0, n0, 0, K, tid);
    CP_COMMIT;
    g_stage(A, Bt, sbase + GST, sbase + GST + 18432, m0, n0, 64, K, tid);
    CP_COMMIT;

    for (int ch = 0; ch < NCH; ch++) {
        if (ch + 1 < NCH) { CP_WAIT(1); } else { CP_WAIT(0); }
        __syncthreads();
        if (ch + 2 < NCH) {
            const uint32_t s = sbase + ((ch + 2) % 3) * GST;
            g_stage(A, Bt, s, s + 18432, m0, n0, (ch + 2) * 64, K, tid);
            CP_COMMIT;
        }
        const uint32_t as = sbase + (ch % 3) * GST;
        g_compute_chunk(as, as + 18432, wm, wn, lane, acc);
        __syncthreads();
    }

    #pragma unroll
    for (int mi = 0; mi < 4; mi++) {
        const int row = m0 + wm + mi * 16 + g;
        #pragma unroll
        for (int nb = 0; nb < 4; nb++) {
            const int col = n0 + wn + nb * 8 + 2 * t;
            const float b0 = bias[col], b1 = bias[col + 1];
            const float sc = (col < DD) ? QSCALE : 1.0f;
            *(uint32_t*)(C + (size_t)row * N + col) =
                pack2((acc[mi][nb][0] + b0) * sc, (acc[mi][nb][1] + b1) * sc);
            *(uint32_t*)(C + (size_t)(row + 8) * N + col) =
                pack2((acc[mi][nb][2] + b0) * sc, (acc[mi][nb][3] + b1) * sc);
        }
    }
}

// ---------------------------------------------------------------------------
// fused kernel (byte-identical to R14): flash [0,768) + out-proj [768,1152)
// ---------------------------------------------------------------------------
#define FROW 144
#define FST  18432
#define FUSED_GRID 1152
#define FUSED_DSM GDSM2

__global__ __launch_bounds__(256, 2) void fused(
    const __half* __restrict__ qkv, __half* __restrict__ y,
    const __half* __restrict__ wot, const float* __restrict__ bo,
    float* __restrict__ out)
{
    extern __shared__ char sm[];
    const uint32_t sbase = smem_u32(sm);
    const int tid = threadIdx.x, warp = tid >> 5, lane = tid & 31;
    const int g = lane >> 2, t = lane & 3;
    const int bid = blockIdx.x;

    if (bid < 768) {
        // ---------------- flash path ----------------
        const int qt = 31 - (bid / 24);            // big tiles first
        const int r24 = bid % 24;
        const int h = r24 % HH, b = r24 / HH;
        const int qbase = qt * 128, wrow = warp * 16;

        const __half* __restrict__ Qg = qkv + (size_t)b * LL * QKV_N + h * DH;
        const __half* __restrict__ Kg = qkv + (size_t)b * LL * QKV_N + DD + h * DH;
        const __half* __restrict__ Vg = qkv + (size_t)b * LL * QKV_N + 2 * DD + h * DH;

        #pragma unroll
        for (int p = 0; p < 4; p++) {
            const int id = p * 256 + tid;
            const int rr = id >> 3, c = id & 7;
            cp16(sbase + rr * FROW + c * 16, Qg + (size_t)(qbase + rr) * QKV_N + c * 8);
        }
        CP_COMMIT; CP_WAIT(0);
        __syncthreads();
        uint32_t qf[4][4];
        #pragma unroll
        for (int j = 0; j < 4; j++)
            ldsm4(qf[j], sbase + (wrow + (lane & 15)) * FROW
                         + (j * 16 + ((lane >> 4) << 3)) * 2);
        __syncthreads();

        float o[8][4] = {};
        float l_lo = 0.f, l_hi = 0.f;
        const int ktmax = 2 * (qt + 1);

        #pragma unroll
        for (int p = 0; p < 2; p++) {
            const int id = p * 256 + tid;
            const int rr = id >> 3, c = id & 7;
            cp16(sbase + rr * FROW + c * 16, Kg + (size_t)rr * QKV_N + c * 8);
            cp16(sbase + 9216 + rr * FROW + c * 16, Vg + (size_t)rr * QKV_N + c * 8);
        }
        CP_COMMIT;

        for (int kt = 0; kt < ktmax; kt++) {
            CP_WAIT(0);
            __syncthreads();
            if (kt + 1 < ktmax) {
                const uint32_t s = sbase + ((kt + 1) & 1) * FST;
                const int nb2 = (kt + 1) * 64;
                #pragma unroll
                for (int p = 0; p < 2; p++) {
                    const int id = p * 256 + tid;
                    const int rr = id >> 3, c = id & 7;
                    cp16(s + rr * FROW + c * 16, Kg + (size_t)(nb2 + rr) * QKV_N + c * 8);
                    cp16(s + 9216 + rr * FROW + c * 16, Vg + (size_t)(nb2 + rr) * QKV_N + c * 8);
                }
                CP_COMMIT;
            }
            const int kbase = kt * 64;
            if (kbase <= qbase + wrow + 15) {
                const uint32_t ks = sbase + (kt & 1) * FST;
                const uint32_t vs = ks + 9216;

                float s[8][4] = {};
                #pragma unroll
                for (int j = 0; j < 4; j++) {
                    const int kk = j * 16;
                    #pragma unroll
                    for (int np = 0; np < 4; np++) {
                        uint32_t bf[4];
                        ldsm4(bf, ks + (np * 16 + (lane & 7) + ((lane >> 4) << 3)) * FROW
                                  + (kk + (((lane >> 3) & 1) << 3)) * 2);
                        mma16(s[np * 2],     qf[j], bf[0], bf[1]);
                        mma16(s[np * 2 + 1], qf[j], bf[2], bf[3]);
                    }
                }

                if (kbase + 63 > qbase + wrow) {
                    const int row_lo = qbase + wrow + g, row_hi = row_lo + 8;
                    #pragma unroll
                    for (int n = 0; n < 8; n++) {
                        const int c0 = kbase + n * 8 + 2 * t;
                        if (c0 > row_lo)     s[n][0] = -FLT_MAX;
                        if (c0 + 1 > row_lo) s[n][1] = -FLT_MAX;
                        if (c0 > row_hi)     s[n][2] = -FLT_MAX;
                        if (c0 + 1 > row_hi) s[n][3] = -FLT_MAX;
                    }
                }

                #pragma unroll
                for (int n = 0; n < 8; n++) {
                    s[n][0] = exp2f(s[n][0]);
                    s[n][1] = exp2f(s[n][1]);
                    s[n][2] = exp2f(s[n][2]);
                    s[n][3] = exp2f(s[n][3]);
                    l_lo += s[n][0] + s[n][1];
                    l_hi += s[n][2] + s[n][3];
                }

                #pragma unroll
                for (int j = 0; j < 4; j++) {
                    uint32_t pa[4];
                    pa[0] = pack2(s[2 * j][0],     s[2 * j][1]);
                    pa[1] = pack2(s[2 * j][2],     s[2 * j][3]);
                    pa[2] = pack2(s[2 * j + 1][0], s[2 * j + 1][1]);
                    pa[3] = pack2(s[2 * j + 1][2], s[2 * j + 1][3]);
                    const int kk = j * 16;
                    #pragma unroll
                    for (int np = 0; np < 4; np++) {
                        uint32_t bf[4];
                        ldsm4t(bf, vs + (kk + (lane & 7) + (((lane >> 3) & 1) << 3)) * FROW
                                   + (np * 16 + ((lane >> 4) << 3)) * 2);
                        mma16(o[np * 2],     pa, bf[0], bf[1]);
                        mma16(o[np * 2 + 1], pa, bf[2], bf[3]);
                    }
                }
            }
        }

        l_lo += __shfl_xor_sync(0xffffffffu, l_lo, 1);
        l_lo += __shfl_xor_sync(0xffffffffu, l_lo, 2);
        l_hi += __shfl_xor_sync(0xffffffffu, l_hi, 1);
        l_hi += __shfl_xor_sync(0xffffffffu, l_hi, 2);

        const float il_lo = 1.0f / l_lo;
        const float il_hi = 1.0f / l_hi;
        const int row = qbase + wrow + g;
        #pragma unroll
        for (int n = 0; n < 8; n++) {
            const int col = h * DH + n * 8 + 2 * t;
            *(uint32_t*)(y + ((size_t)b * LL + row) * DD + col) =
                pack2(o[n][0] * il_lo, o[n][1] * il_lo);
            *(uint32_t*)(y + ((size_t)b * LL + row + 8) * DD + col) =
                pack2(o[n][2] * il_hi, o[n][3] * il_hi);
        }

        __threadfence();
        __syncthreads();
        if (tid == 0) atomicAdd(&g_cnt[b * 32 + qt], 1);

    } else {
        // ---------------- out-proj path ----------------
        const int pid = bid - 768;                 // 0..383
        const int qtp = 31 - (pid / 12);
        const int r12 = pid % 12;
        const int n0 = (r12 % 6) * 128;
        const int pb = r12 / 6;
        const int yy = pb * 32 + qtp;
        const int m0 = yy * 128;

        if (tid == 0) {
            while (atomicAdd(&g_cnt[yy], 0) < HH) __nanosleep(200);
        }
        __syncthreads();
        __threadfence();

        const int wm = (warp >> 2) * 64, wn = (warp & 3) * 32;
        float acc[4][4][4] = {};

        g_stage(y, wot, sbase, sbase + 18432, m0, n0, 0, DD, tid);
        CP_COMMIT;

        const int NCH = DD / 64;
        for (int ch = 0; ch < NCH; ch++) {
            CP_WAIT(0);
            __syncthreads();
            if (ch + 1 < NCH) {
                const uint32_t s = sbase + ((ch + 1) & 1) * GST;
                g_stage(y, wot, s, s + 18432, m0, n0, (ch + 1) * 64, DD, tid);
                CP_COMMIT;
            }
            const uint32_t as = sbase + (ch & 1) * GST;
            g_compute_chunk(as, as + 18432, wm, wn, lane, acc);
            __syncthreads();
        }

        #pragma unroll
        for (int mi = 0; mi < 4; mi++) {
            const int row = m0 + wm + mi * 16 + g;
            #pragma unroll
            for (int nb = 0; nb < 4; nb++) {
                const int col = n0 + wn + nb * 8 + 2 * t;
                const float b0 = bo[col], b1 = bo[col + 1];
                *(float2*)(out + (size_t)row * DD + col) =
                    make_float2(acc[mi][nb][0] + b0, acc[mi][nb][1] + b1);
                *(float2*)(out + (size_t)(row + 8) * DD + col) =
                    make_float2(acc[mi][nb][2] + b0, acc[mi][nb][3] + b1);
            }
        }
    }
}

// ---------------------------------------------------------------------------
extern "C" void kernel_launch(void* const* d_in, const int* in_sizes, int n_in,
                              void* d_out, int out_size)
{
    (void)in_sizes; (void)n_in; (void)out_size;
    const float* x    = (const float*)d_in[0];
    const float* Wqkv = (const float*)d_in[1];
    const float* bqkv = (const float*)d_in[2];
    const float* Wo   = (const float*)d_in[3];
    const float* bo   = (const float*)d_in[4];
    float* out = (float*)d_out;

    __half *xh, *wqkvt, *wot, *qkvh, *yh;
    cudaGetSymbolAddress((void**)&xh, g_xh);
    cudaGetSymbolAddress((void**)&wqkvt, g_wqkvt);
    cudaGetSymbolAddress((void**)&wot, g_wot);
    cudaGetSymbolAddress((void**)&qkvh, g_qkvh);
    cudaGetSymbolAddress((void**)&yh, g_yh);

    static bool attr_done = false;
    if (!attr_done) {
        cudaFuncSetAttribute(gemm_qkv, cudaFuncAttributeMaxDynamicSharedMemorySize, GDSM3);
        cudaFuncSetAttribute(fused, cudaFuncAttributeMaxDynamicSharedMemorySize, FUSED_DSM);
        attr_done = true;
    }

    prep<<<NPREP, 256>>>(x, xh, Wqkv, wqkvt, Wo, wot);

    gemm_qkv<<<dim3(QKV_N / 128, MM / 128), 256, GDSM3>>>(
        xh, wqkvt, bqkv, qkvh, MM, QKV_N, DD);

    fused<<<FUSED_GRID, 256, FUSED_DSM>>>(qkvh, yh, wot, bo, out);
}